// round 10
// baseline (speedup 1.0000x reference)
#include <cuda_runtime.h>
#include <cuda_bf16.h>
#include <math.h>
#include <stdint.h>

#define NROWS 32768
#define C 128
#define H 8
#define NC 64
#define SUBT 4
#define NT (NROWS / 128)
#define KP 136                 // plane row pitch in bf16 elems (272B)
#define PLANEB 34816           // bytes per 128-row plane
#define PLANEE 17408           // elems per plane
#define IMG2 69632             // hi+lo image bytes
#define PITCHF 132

typedef __nv_bfloat16 bf16;

// ---------------- scratch ----------------
__device__ float    g_M_part[NC * H * C * C];        // [c][h][m][i] fp32 partials of phi^T src
__device__ float    g_kss_part[NC * H * C];
__device__ char     g_Mimg[(size_t)H * IMG2];        // M[h] split images (row m, col i)
__device__ uint32_t g_ktvP[H * C * C];               // [h][d][m] packed (B operand for kq)
__device__ float    g_kss[H * C];
__device__ uint32_t g_WcombP[C * C];
__device__ float    g_bcomb[C];
__device__ char     g_qimg[(size_t)NT * IMG2];
__device__ char     g_simg[(size_t)NT * IMG2];
__device__ char     g_wimg[(size_t)24 * IMG2];       // Wq[8],Wk[8],Wv[8]

// ---------------- low-level ----------------
__device__ __forceinline__ uint32_t smem_u32(const void* p) {
    return (uint32_t)__cvta_generic_to_shared(p);
}
__device__ __forceinline__ void ldm4(uint32_t r[4], const bf16* p) {
    uint32_t a = smem_u32(p);
    asm volatile("ldmatrix.sync.aligned.m8n8.x4.shared.b16 {%0,%1,%2,%3}, [%4];"
                 : "=r"(r[0]), "=r"(r[1]), "=r"(r[2]), "=r"(r[3]) : "r"(a));
}
__device__ __forceinline__ void ldm4t(uint32_t r[4], const bf16* p) {
    uint32_t a = smem_u32(p);
    asm volatile("ldmatrix.sync.aligned.m8n8.x4.trans.shared.b16 {%0,%1,%2,%3}, [%4];"
                 : "=r"(r[0]), "=r"(r[1]), "=r"(r[2]), "=r"(r[3]) : "r"(a));
}
__device__ __forceinline__ void mma_bf16(float d[4], const uint32_t a[4],
                                         uint32_t b0, uint32_t b1) {
    asm volatile(
        "mma.sync.aligned.m16n8k16.row.col.f32.bf16.bf16.f32 "
        "{%0,%1,%2,%3},{%4,%5,%6,%7},{%8,%9},{%0,%1,%2,%3};"
        : "+f"(d[0]), "+f"(d[1]), "+f"(d[2]), "+f"(d[3])
        : "r"(a[0]), "r"(a[1]), "r"(a[2]), "r"(a[3]), "r"(b0), "r"(b1));
}
__device__ __forceinline__ uint32_t packf(float x) {
    bf16 h = __float2bfloat16(x);
    bf16 l = __float2bfloat16(x - __bfloat162float(h));
    return (uint32_t)__bfloat16_as_ushort(h) | ((uint32_t)__bfloat16_as_ushort(l) << 16);
}
__device__ __forceinline__ void cpa16(uint32_t d, const void* s) {
    asm volatile("cp.async.cg.shared.global [%0], [%1], 16;" ::"r"(d), "l"(s));
}
#define CP_COMMIT() asm volatile("cp.async.commit_group;" ::: "memory")
#define CP_WAIT0()  asm volatile("cp.async.wait_group 0;" ::: "memory")

// 256-thread async 68KB image copy
__device__ __forceinline__ void copy_img_async(char* dst, const char* __restrict__ src) {
    uint32_t d = smem_u32(dst);
    int tid = threadIdx.x;
#pragma unroll
    for (int it = 0; it < 17; it++) {
        int i = (tid + it * 256) * 16;
        cpa16(d + i, src + i);
    }
}

// packed uint32 rows (stride srow) -> split planes (256 threads)
__device__ __forceinline__ void load_packed(const uint32_t* __restrict__ g, int srow,
                                            char* p) {
    int tid = threadIdx.x;
    char* lo = p + PLANEB;
#pragma unroll
    for (int it = 0; it < 8; it++) {
        int idx = tid + it * 256;
        int row = idx >> 4, c0 = (idx & 15) << 3;
        uint4 pa = *(const uint4*)(g + (size_t)row * srow + c0);
        uint4 pb = *(const uint4*)(g + (size_t)row * srow + c0 + 4);
        int ob = row * 272 + c0 * 2;
        *(uint4*)(p + ob) = make_uint4(
            (pa.x & 0xffffu) | ((pa.y & 0xffffu) << 16),
            (pa.z & 0xffffu) | ((pa.w & 0xffffu) << 16),
            (pb.x & 0xffffu) | ((pb.y & 0xffffu) << 16),
            (pb.z & 0xffffu) | ((pb.w & 0xffffu) << 16));
        *(uint4*)(lo + ob) = make_uint4(
            (pa.x >> 16) | (pa.y & 0xffff0000u),
            (pa.z >> 16) | (pa.w & 0xffff0000u),
            (pb.x >> 16) | (pb.y & 0xffff0000u),
            (pb.z >> 16) | (pb.w & 0xffff0000u));
    }
}

// transposed split store (plane row = feature m, plane col = token r)
__device__ __forceinline__ void storeT_p(char* p, int m, int r, float x) {
    bf16 h = __float2bfloat16(x);
    int ob = m * 272 + r * 2;
    *(bf16*)(p + ob) = h;
    *(bf16*)(p + PLANEB + ob) = __float2bfloat16(x - __bfloat162float(h));
}
// row-major split pair store (row = token, col = even feature c)
__device__ __forceinline__ void storeR_pair(char* p, int row, int c, float x, float y) {
    int ob = row * 272 + c * 2;
    bf16 hx = __float2bfloat16(x), hy = __float2bfloat16(y);
    *(uint32_t*)(p + ob) =
        (uint32_t)__bfloat16_as_ushort(hx) | ((uint32_t)__bfloat16_as_ushort(hy) << 16);
    bf16 lx = __float2bfloat16(x - __bfloat162float(hx));
    bf16 ly = __float2bfloat16(y - __bfloat162float(hy));
    *(uint32_t*)(p + PLANEB + ob) =
        (uint32_t)__bfloat16_as_ushort(lx) | ((uint32_t)__bfloat16_as_ushort(ly) << 16);
}

// 32x64 warp GEMM: rows [mrow,mrow+32) x cols [ncol,ncol+64), K=128, split-bf16 3-pass
// acc[mt][f][j]: rows mrow+mt*16+lane>>2 (j0,j1) / +8 (j2,j3);
// cols ncol+(f>>1)*16+(f&1)*8+2*(lane&3)+{0,1}
__device__ __forceinline__ void wgemm32(float acc[2][8][4], const char* pA, const char* pB,
                                        int mrow, int ncol) {
    const bf16* Ahi = (const bf16*)pA;
    const bf16* Alo = Ahi + PLANEE;
    const bf16* Bhi = (const bf16*)pB;
    const bf16* Blo = Bhi + PLANEE;
    int lane = threadIdx.x & 31;
    int lr = lane & 15, lc = lane >> 4;
#pragma unroll
    for (int kt = 0; kt < 8; kt++) {
        uint32_t ah[2][4], al[2][4];
#pragma unroll
        for (int mt = 0; mt < 2; mt++) {
            int aoff = (mrow + mt * 16 + lr) * KP + kt * 16 + lc * 8;
            ldm4(ah[mt], Ahi + aoff);
            ldm4(al[mt], Alo + aoff);
        }
#pragma unroll
        for (int nb = 0; nb < 4; nb++) {
            int boff = (ncol + nb * 16 + lr) * KP + kt * 16 + lc * 8;
            uint32_t bh[4], bl[4];
            ldm4(bh, Bhi + boff);
            ldm4(bl, Blo + boff);
#pragma unroll
            for (int mt = 0; mt < 2; mt++) {
                mma_bf16(acc[mt][nb * 2], ah[mt], bh[0], bh[2]);
                mma_bf16(acc[mt][nb * 2], ah[mt], bl[0], bl[2]);
                mma_bf16(acc[mt][nb * 2], al[mt], bh[0], bh[2]);
                mma_bf16(acc[mt][nb * 2 + 1], ah[mt], bh[1], bh[3]);
                mma_bf16(acc[mt][nb * 2 + 1], ah[mt], bl[1], bl[3]);
                mma_bf16(acc[mt][nb * 2 + 1], al[mt], bh[1], bh[3]);
            }
        }
    }
}

// trans-B 32x64 warp GEMM: acc[m][i] += sum_r A[m][r] * S[r][i]
// S planes row-major [r][i], loaded with trans ldmatrix.
__device__ __forceinline__ void wgemm32_trans(float acc[2][8][4], const char* pA,
                                              const char* pS, int mrow, int ncol) {
    const bf16* Ahi = (const bf16*)pA;
    const bf16* Alo = Ahi + PLANEE;
    const bf16* Shi = (const bf16*)pS;
    const bf16* Slo = Shi + PLANEE;
    int lane = threadIdx.x & 31;
    int lr = lane & 15, lc = lane >> 4;
#pragma unroll
    for (int kt = 0; kt < 8; kt++) {
        uint32_t ah[2][4], al[2][4];
#pragma unroll
        for (int mt = 0; mt < 2; mt++) {
            int aoff = (mrow + mt * 16 + lr) * KP + kt * 16 + lc * 8;
            ldm4(ah[mt], Ahi + aoff);
            ldm4(al[mt], Alo + aoff);
        }
#pragma unroll
        for (int nb = 0; nb < 4; nb++) {
            int boff = (kt * 16 + lr) * KP + ncol + nb * 16 + lc * 8;
            uint32_t bh[4], bl[4];
            ldm4t(bh, Shi + boff);
            ldm4t(bl, Slo + boff);
#pragma unroll
            for (int mt = 0; mt < 2; mt++) {
                mma_bf16(acc[mt][nb * 2], ah[mt], bh[0], bh[1]);
                mma_bf16(acc[mt][nb * 2], ah[mt], bl[0], bl[1]);
                mma_bf16(acc[mt][nb * 2], al[mt], bh[0], bh[1]);
                mma_bf16(acc[mt][nb * 2 + 1], ah[mt], bh[2], bh[3]);
                mma_bf16(acc[mt][nb * 2 + 1], ah[mt], bl[2], bl[3]);
                mma_bf16(acc[mt][nb * 2 + 1], al[mt], bh[2], bh[3]);
            }
        }
    }
}

#define ZERO2x8x4(a)                                                     \
    _Pragma("unroll") for (int _m = 0; _m < 2; _m++)                     \
    _Pragma("unroll") for (int _f = 0; _f < 8; _f++)                     \
        { a[_m][_f][0] = 0.f; a[_m][_f][1] = 0.f; a[_m][_f][2] = 0.f; a[_m][_f][3] = 0.f; }

// ---------------- kprep ----------------
__global__ void __launch_bounds__(256, 1)
kprep(const float* __restrict__ q, const float* __restrict__ src,
      const float* __restrict__ Wq, const float* __restrict__ Wk,
      const float* __restrict__ Wv) {
    int b = blockIdx.x;
    const float* g;
    char* dst;
    if (b < NT) { g = q + (size_t)b * 128 * C; dst = g_qimg + (size_t)b * IMG2; }
    else if (b < 2 * NT) { g = src + (size_t)(b - NT) * 128 * C; dst = g_simg + (size_t)(b - NT) * IMG2; }
    else {
        int i = b - 2 * NT;
        int mat = i >> 3, h = i & 7;
        g = ((mat == 0) ? Wq : (mat == 1) ? Wk : Wv) + (size_t)h * C * C;
        dst = g_wimg + (size_t)i * IMG2;
    }
    char* lo = dst + PLANEB;
    int tid = threadIdx.x;
#pragma unroll
    for (int it = 0; it < 8; it++) {
        int idx = tid + it * 256;
        int row = idx >> 4, c0 = (idx & 15) << 3;
        float4 a = *(const float4*)(g + (size_t)row * C + c0);
        float4 bb = *(const float4*)(g + (size_t)row * C + c0 + 4);
        float v8[8] = {a.x, a.y, a.z, a.w, bb.x, bb.y, bb.z, bb.w};
        uint32_t hw[4], lw[4];
#pragma unroll
        for (int i2 = 0; i2 < 4; i2++) {
            bf16 h0 = __float2bfloat16(v8[2 * i2]);
            bf16 h1 = __float2bfloat16(v8[2 * i2 + 1]);
            bf16 l0 = __float2bfloat16(v8[2 * i2] - __bfloat162float(h0));
            bf16 l1 = __float2bfloat16(v8[2 * i2 + 1] - __bfloat162float(h1));
            hw[i2] = (uint32_t)__bfloat16_as_ushort(h0) | ((uint32_t)__bfloat16_as_ushort(h1) << 16);
            lw[i2] = (uint32_t)__bfloat16_as_ushort(l0) | ((uint32_t)__bfloat16_as_ushort(l1) << 16);
        }
        int ob = row * 272 + c0 * 2;
        *(uint4*)(dst + ob) = make_uint4(hw[0], hw[1], hw[2], hw[3]);
        *(uint4*)(lo + ob) = make_uint4(lw[0], lw[1], lw[2], lw[3]);
    }
}

// ---------------- kw_comb ----------------
__global__ void __launch_bounds__(256, 1)
kw_comb(const float* __restrict__ Wv, const float* __restrict__ Wvb,
        const float* __restrict__ vmap, const float* __restrict__ vmapb) {
    extern __shared__ char smraw[];
    float* sWb = (float*)smraw;
    int tid = threadIdx.x, lane = tid & 31, w = tid >> 5;
#pragma unroll
    for (int it = 0; it < 64; it++) {
        int idx = tid + it * 256;
        int d = idx >> 7, i = idx & 127;
        float s = 0.f;
#pragma unroll
        for (int h = 0; h < H; h++) s += Wv[((size_t)h * C + d) * C + i];
        sWb[d * PITCHF + i] = s * 0.125f;
    }
    __syncthreads();
    int o = blockIdx.x * 8 + w;
    float r[4] = {0.f, 0.f, 0.f, 0.f};
    for (int d = 0; d < 128; d++) {
        float vm = vmap[(size_t)o * C + d];
#pragma unroll
        for (int k = 0; k < 4; k++) r[k] += vm * sWb[d * PITCHF + lane + 32 * k];
    }
#pragma unroll
    for (int k = 0; k < 4; k++) g_WcombP[(size_t)o * C + lane + 32 * k] = packf(r[k]);
    if (blockIdx.x == 0 && tid < 128) {
        float s = 0.f;
        for (int d = 0; d < 128; d++) {
            float bv = 0.f;
#pragma unroll
            for (int h = 0; h < H; h++) bv += Wvb[h * C + d];
            s += vmap[(size_t)tid * C + d] * (bv * 0.125f);
        }
        g_bcomb[tid] = s + vmapb[tid];
    }
}

// ---------------- K2: per (chunk, head): phi_k -> M += phi^T src, kss ----------------
#define K2_RED (3 * IMG2)
#define K2_BIA (K2_RED + 2048)
__global__ void __launch_bounds__(256, 1)
k2_kv(const float* __restrict__ Wkb, const float* __restrict__ ns) {
    extern __shared__ char sm[];
    char* pA = sm;               // src image
    char* pB = sm + IMG2;        // Wk (static all subtiles)
    char* pP = sm + 2 * IMG2;    // phi^T
    float2* red2 = (float2*)(sm + K2_RED);   // [2][128]
    float* sBk = (float*)(sm + K2_BIA);
    int chunk = blockIdx.x, h = blockIdx.y;
    int tid = threadIdx.x, w = tid >> 5, lane = tid & 31;
    int wm = w & 3, wn = w >> 2;
    int mrow = wm * 32, ncol = wn * 64;
    float ids = 1.f / (fabsf(ns[0]) + 1e-6f);

    if (tid < 128) sBk[tid] = Wkb[h * C + tid];
    float accM[2][8][4];
    ZERO2x8x4(accM);
    float kss_loc = 0.f;

    copy_img_async(pB, g_wimg + (size_t)(8 + h) * IMG2);
    copy_img_async(pA, g_simg + (size_t)(chunk * SUBT) * IMG2);
    CP_COMMIT();

    for (int s = 0; s < SUBT; s++) {
        if (s > 0) {
            __syncthreads();   // prior M-GEMM reads of pA/pP done; red2 free
            copy_img_async(pA, g_simg + (size_t)(chunk * SUBT + s) * IMG2);
            CP_COMMIT();
        }
        CP_WAIT0();
        __syncthreads();       // pA (and pB on s=0) visible; sBk visible

        float acc[2][8][4];
        ZERO2x8x4(acc);
        wgemm32(acc, pA, pB, mrow, ncol);

        float xs[2][8][4];
        float s1[4] = {0.f, 0.f, 0.f, 0.f}, s2[4] = {0.f, 0.f, 0.f, 0.f};
#pragma unroll
        for (int mt = 0; mt < 2; mt++)
#pragma unroll
        for (int f = 0; f < 8; f++) {
            int c = ncol + ((f >> 1) << 4) + ((f & 1) << 3) + ((lane & 3) << 1);
            float b0 = sBk[c], b1 = sBk[c + 1];
            float x;
            x = (fmaxf(acc[mt][f][0] + b0, 0.f) + 1e-6f) * ids; x *= x; xs[mt][f][0] = x; s1[mt * 2] += x; s2[mt * 2] += x * x;
            x = (fmaxf(acc[mt][f][1] + b1, 0.f) + 1e-6f) * ids; x *= x; xs[mt][f][1] = x; s1[mt * 2] += x; s2[mt * 2] += x * x;
            x = (fmaxf(acc[mt][f][2] + b0, 0.f) + 1e-6f) * ids; x *= x; xs[mt][f][2] = x; s1[mt * 2 + 1] += x; s2[mt * 2 + 1] += x * x;
            x = (fmaxf(acc[mt][f][3] + b1, 0.f) + 1e-6f) * ids; x *= x; xs[mt][f][3] = x; s1[mt * 2 + 1] += x; s2[mt * 2 + 1] += x * x;
        }
#pragma unroll
        for (int j = 0; j < 4; j++) {
            s1[j] += __shfl_xor_sync(~0u, s1[j], 1); s1[j] += __shfl_xor_sync(~0u, s1[j], 2);
            s2[j] += __shfl_xor_sync(~0u, s2[j], 1); s2[j] += __shfl_xor_sync(~0u, s2[j], 2);
        }
        if ((lane & 3) == 0) {
#pragma unroll
            for (int mt = 0; mt < 2; mt++) {
                int rA = mrow + mt * 16 + (lane >> 2);
                red2[wn * 128 + rA] = make_float2(s1[mt * 2], s2[mt * 2]);
                red2[wn * 128 + rA + 8] = make_float2(s1[mt * 2 + 1], s2[mt * 2 + 1]);
            }
        }
        __syncthreads();   // red2 visible
        float sc[4];
#pragma unroll
        for (int mt = 0; mt < 2; mt++) {
            int rA = mrow + mt * 16 + (lane >> 2);
            float2 a0 = red2[rA], a1 = red2[128 + rA];
            sc[mt * 2] = sqrtf(a0.x + a1.x) / (sqrtf(a0.y + a1.y) + 1e-8f);
            float2 b0v = red2[rA + 8], b1v = red2[128 + rA + 8];
            sc[mt * 2 + 1] = sqrtf(b0v.x + b1v.x) / (sqrtf(b0v.y + b1v.y) + 1e-8f);
        }
#pragma unroll
        for (int mt = 0; mt < 2; mt++) {
            int rA = mrow + mt * 16 + (lane >> 2), rB = rA + 8;
#pragma unroll
            for (int f = 0; f < 8; f++) {
                int c = ncol + ((f >> 1) << 4) + ((f & 1) << 3) + ((lane & 3) << 1);
                storeT_p(pP, c, rA, xs[mt][f][0] * sc[mt * 2]);
                storeT_p(pP, c + 1, rA, xs[mt][f][1] * sc[mt * 2]);
                storeT_p(pP, c, rB, xs[mt][f][2] * sc[mt * 2 + 1]);
                storeT_p(pP, c + 1, rB, xs[mt][f][3] * sc[mt * 2 + 1]);
            }
        }
        __syncthreads();   // phi^T fully visible

        // kss partials from phi^T
        if (tid < 128) {
            float s0 = 0.f;
#pragma unroll 8
            for (int r = 0; r < 128; r++) {
                int ob = tid * 272 + r * 2;
                s0 += __bfloat162float(*(bf16*)(pP + ob)) +
                      __bfloat162float(*(bf16*)(pP + PLANEB + ob));
            }
            kss_loc += s0;
        }
        // M accumulate: [m][i] += phi^T (A) x src (trans B)
        wgemm32_trans(accM, pP, pA, mrow, ncol);
    }

    size_t base = ((size_t)(chunk * H + h)) * C * C;
#pragma unroll
    for (int mt = 0; mt < 2; mt++) {
        int rA = mrow + mt * 16 + (lane >> 2), rB = rA + 8;
#pragma unroll
        for (int f = 0; f < 8; f++) {
            int c = ncol + ((f >> 1) << 4) + ((f & 1) << 3) + ((lane & 3) << 1);
            *(float2*)(g_M_part + base + (size_t)rA * C + c) = make_float2(accM[mt][f][0], accM[mt][f][1]);
            *(float2*)(g_M_part + base + (size_t)rB * C + c) = make_float2(accM[mt][f][2], accM[mt][f][3]);
        }
    }
    if (tid < 128)
        g_kss_part[(size_t)(chunk * H + h) * C + tid] = kss_loc;
}

// ---------------- K2b: reduce M parts -> split image; reduce kss ----------------
__global__ void k2b_reduce() {
    int i = blockIdx.x * blockDim.x + threadIdx.x;
    int h = i >> 14, rem = i & 16383, m = rem >> 7, ii = rem & 127;
    float s = 0.f;
#pragma unroll 8
    for (int c = 0; c < NC; c++) s += g_M_part[(size_t)c * (H * C * C) + i];
    char* img = g_Mimg + (size_t)h * IMG2;
    int ob = m * 272 + ii * 2;
    bf16 hi = __float2bfloat16(s);
    *(bf16*)(img + ob) = hi;
    *(bf16*)(img + PLANEB + ob) = __float2bfloat16(s - __bfloat162float(hi));
    if (i < H * C) {
        float s2 = 0.f;
#pragma unroll 8
        for (int c = 0; c < NC; c++) s2 += g_kss_part[(size_t)c * (H * C) + i];
        g_kss[i] = s2;
    }
}

// ---------------- K2c: KtV[h] = M[h] @ Wv[h]^T + kss⊗b -> packed [d][m] ----------------
__global__ void __launch_bounds__(256, 1)
k2c_ktv(const float* __restrict__ Wvb) {
    extern __shared__ char sm[];
    char* pA = sm;
    char* pB = sm + IMG2;
    float* sKss = (float*)(sm + 2 * IMG2);
    float* sBv = sKss + 128;
    int h = blockIdx.x;
    int tid = threadIdx.x, w = tid >> 5, lane = tid & 31;
    int wm = w & 3, wn = w >> 2;
    int mrow = wm * 32, ncol = wn * 64;

    copy_img_async(pA, g_Mimg + (size_t)h * IMG2);
    copy_img_async(pB, g_wimg + (size_t)(16 + h) * IMG2);
    CP_COMMIT();
    if (tid < 128) {
        sKss[tid] = g_kss[h * C + tid];
        sBv[tid] = Wvb[h * C + tid];
    }
    CP_WAIT0();
    __syncthreads();

    float acc[2][8][4];
    ZERO2x8x4(acc);
    wgemm32(acc, pA, pB, mrow, ncol);
    uint32_t* gp = g_ktvP + ((size_t)h << 14);
#pragma unroll
    for (int mt = 0; mt < 2; mt++) {
        int rA = mrow + mt * 16 + (lane >> 2), rB = rA + 8;
        float kssA = sKss[rA], kssB = sKss[rB];
#pragma unroll
        for (int f = 0; f < 8; f++) {
            int c = ncol + ((f >> 1) << 4) + ((f & 1) << 3) + ((lane & 3) << 1);
            gp[(size_t)c * C + rA] = packf(acc[mt][f][0] + kssA * sBv[c]);
            gp[(size_t)(c + 1) * C + rA] = packf(acc[mt][f][1] + kssA * sBv[c + 1]);
            gp[(size_t)c * C + rB] = packf(acc[mt][f][2] + kssB * sBv[c]);
            gp[(size_t)(c + 1) * C + rB] = packf(acc[mt][f][3] + kssB * sBv[c + 1]);
        }
    }
}

// ---------------- KQ: fused phi_q + numerator + comb + epilogue ----------------
#define KQ_RED (3 * IMG2)
#define KQ_BIA (KQ_RED + 4096)
__global__ void __launch_bounds__(256, 1)
kq_fused(const float* __restrict__ Wqb, const float* __restrict__ ns,
         float* __restrict__ out) {
    extern __shared__ char sm[];
    char* pA = sm;               // q image (persistent), then src
    char* pB = sm + IMG2;        // Wq[h] -> phi (row-major) ; then Wcomb
    char* pC = sm + 2 * IMG2;    // ktvP[h] planes
    float4* red4 = (float4*)(sm + KQ_RED);   // [2][128]
    float* sBias = (float*)(sm + KQ_BIA);
    float* sKs = sBias + 128;
    float* sBc = sKs + 128;
    int t = blockIdx.x, n0 = t * 128;
    int tid = threadIdx.x, w = tid >> 5, lane = tid & 31;
    int wm = w & 3, wn = w >> 2;
    int mrow = wm * 32, ncol = wn * 64;
    float ids = 1.f / (fabsf(ns[0]) + 1e-6f);

    copy_img_async(pA, g_qimg + (size_t)t * IMG2);
    CP_COMMIT();
    if (tid < 128) sBc[tid] = g_bcomb[tid];

    float outacc[2][8][4];
    ZERO2x8x4(outacc);

    for (int h = 0; h < H; h++) {
        __syncthreads();   // prior GEMM2 reads of pB/pC done; red4 free
        copy_img_async(pB, g_wimg + (size_t)h * IMG2);
        CP_COMMIT();
        load_packed(g_ktvP + ((size_t)h << 14), C, pC);
        if (tid < 128) {
            sBias[tid] = Wqb[h * C + tid];
            sKs[tid] = g_kss[h * C + tid];
        }
        CP_WAIT0();
        __syncthreads();

        float acc[2][8][4];
        ZERO2x8x4(acc);
        wgemm32(acc, pA, pB, mrow, ncol);

        float xs[2][8][4];
        float s1[4] = {0.f, 0.f, 0.f, 0.f}, s2[4] = {0.f, 0.f, 0.f, 0.f},
              sd[4] = {0.f, 0.f, 0.f, 0.f};
#pragma unroll
        for (int mt = 0; mt < 2; mt++)
#pragma unroll
        for (int f = 0; f < 8; f++) {
            int c = ncol + ((f >> 1) << 4) + ((f & 1) << 3) + ((lane & 3) << 1);
            float b0 = sBias[c], b1 = sBias[c + 1];
            float k0 = sKs[c], k1 = sKs[c + 1];
            float x;
            x = (fmaxf(acc[mt][f][0] + b0, 0.f) + 1e-6f) * ids; x *= x; xs[mt][f][0] = x; s1[mt * 2] += x; s2[mt * 2] += x * x; sd[mt * 2] += x * k0;
            x = (fmaxf(acc[mt][f][1] + b1, 0.f) + 1e-6f) * ids; x *= x; xs[mt][f][1] = x; s1[mt * 2] += x; s2[mt * 2] += x * x; sd[mt * 2] += x * k1;
            x = (fmaxf(acc[mt][f][2] + b0, 0.f) + 1e-6f) * ids; x *= x; xs[mt][f][2] = x; s1[mt * 2 + 1] += x; s2[mt * 2 + 1] += x * x; sd[mt * 2 + 1] += x * k0;
            x = (fmaxf(acc[mt][f][3] + b1, 0.f) + 1e-6f) * ids; x *= x; xs[mt][f][3] = x; s1[mt * 2 + 1] += x; s2[mt * 2 + 1] += x * x; sd[mt * 2 + 1] += x * k1;
        }
#pragma unroll
        for (int j = 0; j < 4; j++) {
            s1[j] += __shfl_xor_sync(~0u, s1[j], 1); s1[j] += __shfl_xor_sync(~0u, s1[j], 2);
            s2[j] += __shfl_xor_sync(~0u, s2[j], 1); s2[j] += __shfl_xor_sync(~0u, s2[j], 2);
            sd[j] += __shfl_xor_sync(~0u, sd[j], 1); sd[j] += __shfl_xor_sync(~0u, sd[j], 2);
        }
        if ((lane & 3) == 0) {
#pragma unroll
            for (int mt = 0; mt < 2; mt++) {
                int rA = mrow + mt * 16 + (lane >> 2);
                red4[wn * 128 + rA] = make_float4(s1[mt * 2], s2[mt * 2], sd[mt * 2], 0.f);
                red4[wn * 128 + rA + 8] = make_float4(s1[mt * 2 + 1], s2[mt * 2 + 1], sd[mt * 2 + 1], 0.f);
            }
        }
        __syncthreads();   // red4 visible; all warps done reading pB (Wq)
        float sc[4], den[4];
#pragma unroll
        for (int mt = 0; mt < 2; mt++) {
            int rA = mrow + mt * 16 + (lane >> 2);
            float4 a0 = red4[rA], a1 = red4[128 + rA];
            sc[mt * 2] = sqrtf(a0.x + a1.x) / (sqrtf(a0.y + a1.y) + 1e-8f);
            den[mt * 2] = 0.125f / (sc[mt * 2] * (a0.z + a1.z) + 1e-6f);
            float4 b0v = red4[rA + 8], b1v = red4[128 + rA + 8];
            sc[mt * 2 + 1] = sqrtf(b0v.x + b1v.x) / (sqrtf(b0v.y + b1v.y) + 1e-8f);
            den[mt * 2 + 1] = 0.125f / (sc[mt * 2 + 1] * (b0v.z + b1v.z) + 1e-6f);
        }
        // phi row-major into pB (rows span both col-half warps -> syncthreads below)
#pragma unroll
        for (int mt = 0; mt < 2; mt++) {
            int rA = mrow + mt * 16 + (lane >> 2), rB = rA + 8;
#pragma unroll
            for (int f = 0; f < 8; f++) {
                int c = ncol + ((f >> 1) << 4) + ((f & 1) << 3) + ((lane & 3) << 1);
                storeR_pair(pB, rA, c, xs[mt][f][0] * sc[mt * 2], xs[mt][f][1] * sc[mt * 2]);
                storeR_pair(pB, rB, c, xs[mt][f][2] * sc[mt * 2 + 1], xs[mt][f][3] * sc[mt * 2 + 1]);
            }
        }
        __syncthreads();   // full phi visible

        // numerator GEMM: phi @ ktv
        ZERO2x8x4(acc);
        wgemm32(acc, pB, pC, mrow, ncol);
#pragma unroll
        for (int mt = 0; mt < 2; mt++)
#pragma unroll
        for (int f = 0; f < 8; f++) {
            outacc[mt][f][0] += acc[mt][f][0] * den[mt * 2];
            outacc[mt][f][1] += acc[mt][f][1] * den[mt * 2];
            outacc[mt][f][2] += acc[mt][f][2] * den[mt * 2 + 1];
            outacc[mt][f][3] += acc[mt][f][3] * den[mt * 2 + 1];
        }
    }

    // comb (vss branch)
    __syncthreads();
    copy_img_async(pA, g_simg + (size_t)t * IMG2);
    CP_COMMIT();
    load_packed(g_WcombP, C, pB);
    CP_WAIT0();
    __syncthreads();
    {
        float acc[2][8][4];
        ZERO2x8x4(acc);
        wgemm32(acc, pA, pB, mrow, ncol);
#pragma unroll
        for (int mt = 0; mt < 2; mt++)
#pragma unroll
        for (int f = 0; f < 8; f++) {
            int c = ncol + ((f >> 1) << 4) + ((f & 1) << 3) + ((lane & 3) << 1);
            outacc[mt][f][0] += acc[mt][f][0] + sBc[c];
            outacc[mt][f][1] += acc[mt][f][1] + sBc[c + 1];
            outacc[mt][f][2] += acc[mt][f][2] + sBc[c];
            outacc[mt][f][3] += acc[mt][f][3] + sBc[c + 1];
        }
    }

    // time coordinate (cross-warp over col halves)
    float ssq[4] = {0.f, 0.f, 0.f, 0.f};
#pragma unroll
    for (int mt = 0; mt < 2; mt++)
#pragma unroll
    for (int f = 0; f < 8; f++) {
        ssq[mt * 2] += outacc[mt][f][0] * outacc[mt][f][0] + outacc[mt][f][1] * outacc[mt][f][1];
        ssq[mt * 2 + 1] += outacc[mt][f][2] * outacc[mt][f][2] + outacc[mt][f][3] * outacc[mt][f][3];
    }
#pragma unroll
    for (int j = 0; j < 4; j++) {
        ssq[j] += __shfl_xor_sync(~0u, ssq[j], 1);
        ssq[j] += __shfl_xor_sync(~0u, ssq[j], 2);
    }
    if ((lane & 3) == 0) {
#pragma unroll
        for (int mt = 0; mt < 2; mt++) {
            int rA = mrow + mt * 16 + (lane >> 2);
            red4[wn * 128 + rA] = make_float4(ssq[mt * 2], 0.f, 0.f, 0.f);
            red4[wn * 128 + rA + 8] = make_float4(ssq[mt * 2 + 1], 0.f, 0.f, 0.f);
        }
    }
    __syncthreads();
#pragma unroll
    for (int mt = 0; mt < 2; mt++) {
        int rA = mrow + mt * 16 + (lane >> 2), rB = rA + 8;
        float totA = red4[rA].x + red4[128 + rA].x;
        float totB = red4[rB].x + red4[128 + rB].x;
        float* rowA = out + (size_t)(n0 + rA) * 129;
        float* rowB = out + (size_t)(n0 + rB) * 129;
        if (wn == 0 && (lane & 3) == 0) {
            rowA[0] = sqrtf(totA + 1.0f);
            rowB[0] = sqrtf(totB + 1.0f);
        }
#pragma unroll
        for (int f = 0; f < 8; f++) {
            int c = ncol + ((f >> 1) << 4) + ((f & 1) << 3) + ((lane & 3) << 1);
            rowA[1 + c] = outacc[mt][f][0];
            rowA[2 + c] = outacc[mt][f][1];
            rowB[1 + c] = outacc[mt][f][2];
            rowB[2 + c] = outacc[mt][f][3];
        }
    }
}

// ---------------- launch ----------------
extern "C" void kernel_launch(void* const* d_in, const int* in_sizes, int n_in,
                              void* d_out, int out_size) {
    const float* q     = (const float*)d_in[0];
    const float* src   = (const float*)d_in[1];
    const float* Wq    = (const float*)d_in[2];
    const float* Wqb   = (const float*)d_in[3];
    const float* Wk    = (const float*)d_in[4];
    const float* Wkb   = (const float*)d_in[5];
    const float* Wv    = (const float*)d_in[6];
    const float* Wvb   = (const float*)d_in[7];
    const float* vmap  = (const float*)d_in[8];
    const float* vmapb = (const float*)d_in[9];
    const float* ns    = (const float*)d_in[10];
    float* out = (float*)d_out;

    size_t sm2 = (size_t)3 * IMG2 + 2048 + 512;    // ~211.5 KB
    size_t smc = (size_t)2 * IMG2 + 1024;          // ~140.3 KB
    size_t smq = (size_t)3 * IMG2 + 4096 + 1536;   // ~214.5 KB
    size_t smw = (size_t)128 * PITCHF * 4;         // 67,584 B
    cudaFuncSetAttribute(k2_kv,    cudaFuncAttributeMaxDynamicSharedMemorySize, (int)sm2);
    cudaFuncSetAttribute(k2c_ktv,  cudaFuncAttributeMaxDynamicSharedMemorySize, (int)smc);
    cudaFuncSetAttribute(kq_fused, cudaFuncAttributeMaxDynamicSharedMemorySize, (int)smq);
    cudaFuncSetAttribute(kw_comb,  cudaFuncAttributeMaxDynamicSharedMemorySize, (int)smw);

    kprep<<<2 * NT + 24, 256>>>(q, src, Wq, Wk, Wv);
    kw_comb<<<16, 256, smw>>>(Wv, Wvb, vmap, vmapb);
    k2_kv<<<dim3(NC, H), 256, sm2>>>(Wkb, ns);
    k2b_reduce<<<(H * C * C) / 256, 256>>>();
    k2c_ktv<<<H, 256, smc>>>(Wvb);
    kq_fused<<<NT, 256, smq>>>(Wqb, ns, out);
}

// round 11
// speedup vs baseline: 1.0983x; 1.0983x over previous
#include <cuda_runtime.h>
#include <cuda_bf16.h>
#include <math.h>
#include <stdint.h>

#define NROWS 32768
#define C 128
#define H 8
#define NC 64
#define SUBT 4
#define NT (NROWS / 128)
#define KP 136                 // plane row pitch in bf16 elems (272B)
#define PLANEB 34816           // bytes per 128-row plane
#define PLANEE 17408           // elems per plane
#define IMG2 69632             // hi+lo image bytes
#define PITCHF 132

typedef __nv_bfloat16 bf16;

// ---------------- scratch ----------------
__device__ float    g_M_part[NC * H * C * C];        // [c][h][m][i] fp32 partials of phi^T src
__device__ float    g_kss_part[NC * H * C];
__device__ char     g_Mimg[(size_t)H * IMG2];        // M[h] split images (row m, col i)
__device__ char     g_ktvImg[(size_t)H * IMG2];      // KtV[h] split images (row d, col m)
__device__ float    g_kss[H * C];
__device__ char     g_WcombImg[IMG2];                // Wcomb split image (row o, col i)
__device__ float    g_bcomb[C];
__device__ char     g_qimg[(size_t)NT * IMG2];
__device__ char     g_simg[(size_t)NT * IMG2];
__device__ char     g_wimg[(size_t)24 * IMG2];       // Wq[8],Wk[8],Wv[8]

// ---------------- low-level ----------------
__device__ __forceinline__ uint32_t smem_u32(const void* p) {
    return (uint32_t)__cvta_generic_to_shared(p);
}
__device__ __forceinline__ void ldm4(uint32_t r[4], const bf16* p) {
    uint32_t a = smem_u32(p);
    asm volatile("ldmatrix.sync.aligned.m8n8.x4.shared.b16 {%0,%1,%2,%3}, [%4];"
                 : "=r"(r[0]), "=r"(r[1]), "=r"(r[2]), "=r"(r[3]) : "r"(a));
}
__device__ __forceinline__ void ldm4t(uint32_t r[4], const bf16* p) {
    uint32_t a = smem_u32(p);
    asm volatile("ldmatrix.sync.aligned.m8n8.x4.trans.shared.b16 {%0,%1,%2,%3}, [%4];"
                 : "=r"(r[0]), "=r"(r[1]), "=r"(r[2]), "=r"(r[3]) : "r"(a));
}
__device__ __forceinline__ void mma_bf16(float d[4], const uint32_t a[4],
                                         uint32_t b0, uint32_t b1) {
    asm volatile(
        "mma.sync.aligned.m16n8k16.row.col.f32.bf16.bf16.f32 "
        "{%0,%1,%2,%3},{%4,%5,%6,%7},{%8,%9},{%0,%1,%2,%3};"
        : "+f"(d[0]), "+f"(d[1]), "+f"(d[2]), "+f"(d[3])
        : "r"(a[0]), "r"(a[1]), "r"(a[2]), "r"(a[3]), "r"(b0), "r"(b1));
}
__device__ __forceinline__ uint32_t bf2pack(bf16 x, bf16 y) {
    return (uint32_t)__bfloat16_as_ushort(x) | ((uint32_t)__bfloat16_as_ushort(y) << 16);
}
__device__ __forceinline__ void cpa16(uint32_t d, const void* s) {
    asm volatile("cp.async.cg.shared.global [%0], [%1], 16;" ::"r"(d), "l"(s));
}
#define CP_COMMIT() asm volatile("cp.async.commit_group;" ::: "memory")
#define CP_WAIT0()  asm volatile("cp.async.wait_group 0;" ::: "memory")
#define CP_WAIT1()  asm volatile("cp.async.wait_group 1;" ::: "memory")

// 256-thread async 68KB image copy
__device__ __forceinline__ void copy_img_async(char* dst, const char* __restrict__ src) {
    uint32_t d = smem_u32(dst);
    int tid = threadIdx.x;
#pragma unroll
    for (int it = 0; it < 17; it++) {
        int i = (tid + it * 256) * 16;
        cpa16(d + i, src + i);
    }
}

// transposed split store (plane row = feature m, plane col = token r); works gmem/smem
__device__ __forceinline__ void storeT_p(char* p, int m, int r, float x) {
    bf16 h = __float2bfloat16(x);
    int ob = m * 272 + r * 2;
    *(bf16*)(p + ob) = h;
    *(bf16*)(p + PLANEB + ob) = __float2bfloat16(x - __bfloat162float(h));
}

// full-width warp GEMM: rows [mrow,mrow+16) x 128 cols, K=128, split-bf16 3-pass
// acc[f][j]: f covers cols (f>>1)*16+(f&1)*8+2*(lane&3)+{0,1}; rows lane>>2 / +8
__device__ __forceinline__ void wgemm(float acc[16][4], const char* pA, const char* pB,
                                      int mrow) {
    const bf16* Ahi = (const bf16*)pA;
    const bf16* Alo = Ahi + PLANEE;
    const bf16* Bhi = (const bf16*)pB;
    const bf16* Blo = Bhi + PLANEE;
    int lane = threadIdx.x & 31;
    int lr = lane & 15, lc = lane >> 4;
#pragma unroll
    for (int kt = 0; kt < 8; kt++) {
        int aoff = (mrow + lr) * KP + kt * 16 + lc * 8;
        uint32_t ah[4], al[4];
        ldm4(ah, Ahi + aoff);
        ldm4(al, Alo + aoff);
#pragma unroll
        for (int nt = 0; nt < 8; nt++) {
            int boff = (nt * 16 + lr) * KP + kt * 16 + lc * 8;
            uint32_t bh[4], bl[4];
            ldm4(bh, Bhi + boff);
            ldm4(bl, Blo + boff);
            mma_bf16(acc[nt * 2], ah, bh[0], bh[2]);
            mma_bf16(acc[nt * 2], ah, bl[0], bl[2]);
            mma_bf16(acc[nt * 2], al, bh[0], bh[2]);
            mma_bf16(acc[nt * 2 + 1], ah, bh[1], bh[3]);
            mma_bf16(acc[nt * 2 + 1], ah, bl[1], bl[3]);
            mma_bf16(acc[nt * 2 + 1], al, bh[1], bh[3]);
        }
    }
}

// GEMM with A fragments already in registers (ph/pl[kt][0..3]); B split image in smem
__device__ __forceinline__ void wgemm_regA(float acc[16][4],
                                           const uint32_t ph[8][4], const uint32_t pl[8][4],
                                           const char* pB) {
    const bf16* Bhi = (const bf16*)pB;
    const bf16* Blo = Bhi + PLANEE;
    int lane = threadIdx.x & 31;
    int lr = lane & 15, lc = lane >> 4;
#pragma unroll
    for (int kt = 0; kt < 8; kt++) {
#pragma unroll
        for (int nt = 0; nt < 8; nt++) {
            int boff = (nt * 16 + lr) * KP + kt * 16 + lc * 8;
            uint32_t bh[4], bl[4];
            ldm4(bh, Bhi + boff);
            ldm4(bl, Blo + boff);
            mma_bf16(acc[nt * 2], ph[kt], bh[0], bh[2]);
            mma_bf16(acc[nt * 2], ph[kt], bl[0], bl[2]);
            mma_bf16(acc[nt * 2], pl[kt], bh[0], bh[2]);
            mma_bf16(acc[nt * 2 + 1], ph[kt], bh[1], bh[3]);
            mma_bf16(acc[nt * 2 + 1], ph[kt], bl[1], bl[3]);
            mma_bf16(acc[nt * 2 + 1], pl[kt], bh[1], bh[3]);
        }
    }
}

// trans-B warp GEMM: acc[m][i] += sum_r A[m][r] * S[r][i]
__device__ __forceinline__ void wgemm_trans(float acc[16][4], const char* pA, const char* pS,
                                            int mrow) {
    const bf16* Ahi = (const bf16*)pA;
    const bf16* Alo = Ahi + PLANEE;
    const bf16* Shi = (const bf16*)pS;
    const bf16* Slo = Shi + PLANEE;
    int lane = threadIdx.x & 31;
    int lr = lane & 15, lc = lane >> 4;
#pragma unroll
    for (int kt = 0; kt < 8; kt++) {
        int aoff = (mrow + lr) * KP + kt * 16 + lc * 8;
        uint32_t ah[4], al[4];
        ldm4(ah, Ahi + aoff);
        ldm4(al, Alo + aoff);
#pragma unroll
        for (int nt = 0; nt < 8; nt++) {
            int boff = (kt * 16 + lr) * KP + nt * 16 + lc * 8;
            uint32_t bh[4], bl[4];
            ldm4t(bh, Shi + boff);
            ldm4t(bl, Slo + boff);
            mma_bf16(acc[nt * 2], ah, bh[0], bh[1]);
            mma_bf16(acc[nt * 2], ah, bl[0], bl[1]);
            mma_bf16(acc[nt * 2], al, bh[0], bh[1]);
            mma_bf16(acc[nt * 2 + 1], ah, bh[2], bh[3]);
            mma_bf16(acc[nt * 2 + 1], ah, bl[2], bl[3]);
            mma_bf16(acc[nt * 2 + 1], al, bh[2], bh[3]);
        }
    }
}

#define ZERO16x4(a)                                   \
    _Pragma("unroll") for (int _f = 0; _f < 16; _f++) \
        { a[_f][0] = 0.f; a[_f][1] = 0.f; a[_f][2] = 0.f; a[_f][3] = 0.f; }

// ---------------- kprep: fp32 -> split-bf16 images ----------------
__global__ void __launch_bounds__(256, 1)
kprep(const float* __restrict__ q, const float* __restrict__ src,
      const float* __restrict__ Wq, const float* __restrict__ Wk,
      const float* __restrict__ Wv) {
    int b = blockIdx.x;
    const float* g;
    char* dst;
    if (b < NT) { g = q + (size_t)b * 128 * C; dst = g_qimg + (size_t)b * IMG2; }
    else if (b < 2 * NT) { g = src + (size_t)(b - NT) * 128 * C; dst = g_simg + (size_t)(b - NT) * IMG2; }
    else {
        int i = b - 2 * NT;
        int mat = i >> 3, h = i & 7;
        g = ((mat == 0) ? Wq : (mat == 1) ? Wk : Wv) + (size_t)h * C * C;
        dst = g_wimg + (size_t)i * IMG2;
    }
    char* lo = dst + PLANEB;
    int tid = threadIdx.x;
#pragma unroll
    for (int it = 0; it < 8; it++) {
        int idx = tid + it * 256;
        int row = idx >> 4, c0 = (idx & 15) << 3;
        float4 a = *(const float4*)(g + (size_t)row * C + c0);
        float4 bb = *(const float4*)(g + (size_t)row * C + c0 + 4);
        float v8[8] = {a.x, a.y, a.z, a.w, bb.x, bb.y, bb.z, bb.w};
        uint32_t hw[4], lw[4];
#pragma unroll
        for (int i2 = 0; i2 < 4; i2++) {
            bf16 h0 = __float2bfloat16(v8[2 * i2]);
            bf16 h1 = __float2bfloat16(v8[2 * i2 + 1]);
            bf16 l0 = __float2bfloat16(v8[2 * i2] - __bfloat162float(h0));
            bf16 l1 = __float2bfloat16(v8[2 * i2 + 1] - __bfloat162float(h1));
            hw[i2] = bf2pack(h0, h1);
            lw[i2] = bf2pack(l0, l1);
        }
        int ob = row * 272 + c0 * 2;
        *(uint4*)(dst + ob) = make_uint4(hw[0], hw[1], hw[2], hw[3]);
        *(uint4*)(lo + ob) = make_uint4(lw[0], lw[1], lw[2], lw[3]);
    }
}

// ---------------- kw_comb: combined vss weights -> split image ----------------
__global__ void __launch_bounds__(256, 1)
kw_comb(const float* __restrict__ Wv, const float* __restrict__ Wvb,
        const float* __restrict__ vmap, const float* __restrict__ vmapb) {
    extern __shared__ char smraw[];
    float* sWb = (float*)smraw;
    int tid = threadIdx.x, lane = tid & 31, w = tid >> 5;
#pragma unroll
    for (int it = 0; it < 64; it++) {
        int idx = tid + it * 256;
        int d = idx >> 7, i = idx & 127;
        float s = 0.f;
#pragma unroll
        for (int h = 0; h < H; h++) s += Wv[((size_t)h * C + d) * C + i];
        sWb[d * PITCHF + i] = s * 0.125f;
    }
    __syncthreads();
    int o = blockIdx.x * 8 + w;
    float r[4] = {0.f, 0.f, 0.f, 0.f};
    for (int d = 0; d < 128; d++) {
        float vm = vmap[(size_t)o * C + d];
#pragma unroll
        for (int k = 0; k < 4; k++) r[k] += vm * sWb[d * PITCHF + lane + 32 * k];
    }
#pragma unroll
    for (int k = 0; k < 4; k++) storeT_p(g_WcombImg, o, lane + 32 * k, r[k]);
    if (blockIdx.x == 0 && tid < 128) {
        float s = 0.f;
        for (int d = 0; d < 128; d++) {
            float bv = 0.f;
#pragma unroll
            for (int h = 0; h < H; h++) bv += Wvb[h * C + d];
            s += vmap[(size_t)tid * C + d] * (bv * 0.125f);
        }
        g_bcomb[tid] = s + vmapb[tid];
    }
}

// ---------------- K2: per (chunk, head): phi_k -> M += phi^T src, kss ----------------
#define K2_BIA (3 * IMG2)
__global__ void __launch_bounds__(256, 1)
k2_kv(const float* __restrict__ Wkb, const float* __restrict__ ns) {
    extern __shared__ char sm[];
    char* pA = sm;               // src image
    char* pB = sm + IMG2;        // Wk (static all subtiles)
    char* pP = sm + 2 * IMG2;    // phi^T
    float* sBk = (float*)(sm + K2_BIA);
    int chunk = blockIdx.x, h = blockIdx.y;
    int tid = threadIdx.x, w = tid >> 5, lane = tid & 31;
    int mrow = w * 16;
    int grA = mrow + (lane >> 2), grB = grA + 8;
    float ids = 1.f / (fabsf(ns[0]) + 1e-6f);

    if (tid < 128) sBk[tid] = Wkb[h * C + tid];
    float accM[16][4];
    ZERO16x4(accM);
    float kss_loc = 0.f;

    copy_img_async(pB, g_wimg + (size_t)(8 + h) * IMG2);
    copy_img_async(pA, g_simg + (size_t)(chunk * SUBT) * IMG2);
    CP_COMMIT();

    for (int s = 0; s < SUBT; s++) {
        if (s > 0) {
            __syncthreads();
            copy_img_async(pA, g_simg + (size_t)(chunk * SUBT + s) * IMG2);
            CP_COMMIT();
        }
        CP_WAIT0();
        __syncthreads();

        float acc[16][4];
        ZERO16x4(acc);
        wgemm(acc, pA, pB, mrow);

        float xs[16][4], s1a = 0.f, s2a = 0.f, s1b = 0.f, s2b = 0.f;
#pragma unroll
        for (int f = 0; f < 16; f++) {
            int c = ((f >> 1) << 4) + ((f & 1) << 3) + ((lane & 3) << 1);
            float b0 = sBk[c], b1 = sBk[c + 1];
            float x;
            x = (fmaxf(acc[f][0] + b0, 0.f) + 1e-6f) * ids; x *= x; xs[f][0] = x; s1a += x; s2a += x * x;
            x = (fmaxf(acc[f][1] + b1, 0.f) + 1e-6f) * ids; x *= x; xs[f][1] = x; s1a += x; s2a += x * x;
            x = (fmaxf(acc[f][2] + b0, 0.f) + 1e-6f) * ids; x *= x; xs[f][2] = x; s1b += x; s2b += x * x;
            x = (fmaxf(acc[f][3] + b1, 0.f) + 1e-6f) * ids; x *= x; xs[f][3] = x; s1b += x; s2b += x * x;
        }
        s1a += __shfl_xor_sync(~0u, s1a, 1); s1a += __shfl_xor_sync(~0u, s1a, 2);
        s2a += __shfl_xor_sync(~0u, s2a, 1); s2a += __shfl_xor_sync(~0u, s2a, 2);
        s1b += __shfl_xor_sync(~0u, s1b, 1); s1b += __shfl_xor_sync(~0u, s1b, 2);
        s2b += __shfl_xor_sync(~0u, s2b, 1); s2b += __shfl_xor_sync(~0u, s2b, 2);
        float sca = sqrtf(s1a) / (sqrtf(s2a) + 1e-8f);
        float scb = sqrtf(s1b) / (sqrtf(s2b) + 1e-8f);
#pragma unroll
        for (int f = 0; f < 16; f++) {
            int c = ((f >> 1) << 4) + ((f & 1) << 3) + ((lane & 3) << 1);
            storeT_p(pP, c, grA, xs[f][0] * sca);
            storeT_p(pP, c + 1, grA, xs[f][1] * sca);
            storeT_p(pP, c, grB, xs[f][2] * scb);
            storeT_p(pP, c + 1, grB, xs[f][3] * scb);
        }
        __syncthreads();   // phi^T fully visible

        if (tid < 128) {
            float s0 = 0.f;
#pragma unroll 8
            for (int r = 0; r < 128; r++) {
                int ob = tid * 272 + r * 2;
                s0 += __bfloat162float(*(bf16*)(pP + ob)) +
                      __bfloat162float(*(bf16*)(pP + PLANEB + ob));
            }
            kss_loc += s0;
        }
        wgemm_trans(accM, pP, pA, mrow);
    }

    size_t base = ((size_t)(chunk * H + h)) * C * C;
#pragma unroll
    for (int f = 0; f < 16; f++) {
        int c = ((f >> 1) << 4) + ((f & 1) << 3) + ((lane & 3) << 1);
        *(float2*)(g_M_part + base + (size_t)grA * C + c) = make_float2(accM[f][0], accM[f][1]);
        *(float2*)(g_M_part + base + (size_t)grB * C + c) = make_float2(accM[f][2], accM[f][3]);
    }
    if (tid < 128)
        g_kss_part[(size_t)(chunk * H + h) * C + tid] = kss_loc;
}

// ---------------- K2b: reduce M parts -> split image; reduce kss ----------------
__global__ void k2b_reduce() {
    int i = blockIdx.x * blockDim.x + threadIdx.x;
    int h = i >> 14, rem = i & 16383, m = rem >> 7, ii = rem & 127;
    float s = 0.f;
#pragma unroll 8
    for (int c = 0; c < NC; c++) s += g_M_part[(size_t)c * (H * C * C) + i];
    storeT_p(g_Mimg + (size_t)h * IMG2, m, ii, s);
    if (i < H * C) {
        float s2 = 0.f;
#pragma unroll 8
        for (int c = 0; c < NC; c++) s2 += g_kss_part[(size_t)c * (H * C) + i];
        g_kss[i] = s2;
    }
}

// ---------------- K2c: KtV[h] = M[h] @ Wv[h]^T + kss⊗b -> split image [d][m] ----------------
__global__ void __launch_bounds__(256, 1)
k2c_ktv(const float* __restrict__ Wvb) {
    extern __shared__ char sm[];
    char* pA = sm;
    char* pB = sm + IMG2;
    float* sKss = (float*)(sm + 2 * IMG2);
    float* sBv = sKss + 128;
    int h = blockIdx.x;
    int tid = threadIdx.x, w = tid >> 5, lane = tid & 31;
    int mrow = w * 16;
    int grA = mrow + (lane >> 2), grB = grA + 8;

    copy_img_async(pA, g_Mimg + (size_t)h * IMG2);
    copy_img_async(pB, g_wimg + (size_t)(16 + h) * IMG2);
    CP_COMMIT();
    if (tid < 128) {
        sKss[tid] = g_kss[h * C + tid];
        sBv[tid] = Wvb[h * C + tid];
    }
    CP_WAIT0();
    __syncthreads();

    float acc[16][4];
    ZERO16x4(acc);
    wgemm(acc, pA, pB, mrow);   // acc[m][d] = sum_i M[m][i] Wv[d][i]
    float kssA = sKss[grA], kssB = sKss[grB];
    char* img = g_ktvImg + (size_t)h * IMG2;
#pragma unroll
    for (int f = 0; f < 16; f++) {
        int c = ((f >> 1) << 4) + ((f & 1) << 3) + ((lane & 3) << 1);
        storeT_p(img, c, grA, acc[f][0] + kssA * sBv[c]);
        storeT_p(img, c + 1, grA, acc[f][1] + kssA * sBv[c + 1]);
        storeT_p(img, c, grB, acc[f][2] + kssB * sBv[c]);
        storeT_p(img, c + 1, grB, acc[f][3] + kssB * sBv[c + 1]);
    }
}

// ---------------- KQ: fused phi_q + numerator + comb + epilogue ----------------
#define KQ_MISC (3 * IMG2)
__global__ void __launch_bounds__(256, 1)
kq_fused(const float* __restrict__ Wqb, const float* __restrict__ ns,
         float* __restrict__ out) {
    extern __shared__ char sm[];
    char* pA = sm;               // q image (persistent), then src
    char* pB = sm + IMG2;        // Wq[h] (prefetched), then Wcomb
    char* pC = sm + 2 * IMG2;    // ktv image (prefetched)
    float* sBias = (float*)(sm + KQ_MISC);
    float* sKs = sBias + 128;
    float* sBc = sKs + 128;
    int t = blockIdx.x, n0 = t * 128;
    int tid = threadIdx.x, w = tid >> 5, lane = tid & 31;
    int mrow = w * 16;
    int grA = mrow + (lane >> 2), grB = grA + 8;
    float ids = 1.f / (fabsf(ns[0]) + 1e-6f);

    // group 1: pA + pB(0); group 2: pC(0)
    copy_img_async(pA, g_qimg + (size_t)t * IMG2);
    copy_img_async(pB, g_wimg);
    CP_COMMIT();
    copy_img_async(pC, g_ktvImg);
    CP_COMMIT();
    if (tid < 128) sBc[tid] = g_bcomb[tid];

    float outacc[16][4];
    ZERO16x4(outacc);

    for (int h = 0; h < H; h++) {
        CP_WAIT1();        // pA + pB(h) ready (pC(h) may still be in flight)
        if (tid < 128) {
            sBias[tid] = Wqb[h * C + tid];
            sKs[tid] = g_kss[h * C + tid];
        }
        __syncthreads();

        float acc[16][4];
        ZERO16x4(acc);
        wgemm(acc, pA, pB, mrow);

        float xs[16][4];
        float s1a = 0.f, s2a = 0.f, sda = 0.f, s1b = 0.f, s2b = 0.f, sdb = 0.f;
#pragma unroll
        for (int f = 0; f < 16; f++) {
            int c = ((f >> 1) << 4) + ((f & 1) << 3) + ((lane & 3) << 1);
            float b0 = sBias[c], b1 = sBias[c + 1];
            float k0 = sKs[c], k1 = sKs[c + 1];
            float x;
            x = (fmaxf(acc[f][0] + b0, 0.f) + 1e-6f) * ids; x *= x; xs[f][0] = x; s1a += x; s2a += x * x; sda += x * k0;
            x = (fmaxf(acc[f][1] + b1, 0.f) + 1e-6f) * ids; x *= x; xs[f][1] = x; s1a += x; s2a += x * x; sda += x * k1;
            x = (fmaxf(acc[f][2] + b0, 0.f) + 1e-6f) * ids; x *= x; xs[f][2] = x; s1b += x; s2b += x * x; sdb += x * k0;
            x = (fmaxf(acc[f][3] + b1, 0.f) + 1e-6f) * ids; x *= x; xs[f][3] = x; s1b += x; s2b += x * x; sdb += x * k1;
        }
        s1a += __shfl_xor_sync(~0u, s1a, 1); s1a += __shfl_xor_sync(~0u, s1a, 2);
        s2a += __shfl_xor_sync(~0u, s2a, 1); s2a += __shfl_xor_sync(~0u, s2a, 2);
        sda += __shfl_xor_sync(~0u, sda, 1); sda += __shfl_xor_sync(~0u, sda, 2);
        s1b += __shfl_xor_sync(~0u, s1b, 1); s1b += __shfl_xor_sync(~0u, s1b, 2);
        s2b += __shfl_xor_sync(~0u, s2b, 1); s2b += __shfl_xor_sync(~0u, s2b, 2);
        sdb += __shfl_xor_sync(~0u, sdb, 1); sdb += __shfl_xor_sync(~0u, sdb, 2);
        float sca = sqrtf(s1a) / (sqrtf(s2a) + 1e-8f);
        float scb = sqrtf(s1b) / (sqrtf(s2b) + 1e-8f);
        float denA = 0.125f / (sca * sda + 1e-6f);
        float denB = 0.125f / (scb * sdb + 1e-6f);

        // phi -> A fragments entirely in registers (no smem round trip)
        uint32_t ph[8][4], pl[8][4];
#pragma unroll
        for (int kt = 0; kt < 8; kt++) {
#pragma unroll
            for (int half = 0; half < 2; half++) {
                int f = 2 * kt + half;
                float v0 = xs[f][0] * sca, v1 = xs[f][1] * sca;
                float v2 = xs[f][2] * scb, v3 = xs[f][3] * scb;
                bf16 h0 = __float2bfloat16(v0), h1 = __float2bfloat16(v1);
                bf16 h2 = __float2bfloat16(v2), h3 = __float2bfloat16(v3);
                ph[kt][half * 2] = bf2pack(h0, h1);       // row rA
                ph[kt][half * 2 + 1] = bf2pack(h2, h3);   // row rB
                pl[kt][half * 2] = bf2pack(__float2bfloat16(v0 - __bfloat162float(h0)),
                                           __float2bfloat16(v1 - __bfloat162float(h1)));
                pl[kt][half * 2 + 1] = bf2pack(__float2bfloat16(v2 - __bfloat162float(h2)),
                                               __float2bfloat16(v3 - __bfloat162float(h3)));
            }
        }

        __syncthreads();   // all warps done reading pB(h)
        int hn = (h < 7) ? h + 1 : 7;
        copy_img_async(pB, g_wimg + (size_t)hn * IMG2);   // overlaps gemm2
        CP_COMMIT();
        CP_WAIT1();        // pC(h) done (pB(hn) may be pending)
        __syncthreads();   // pC visible to all warps

        // numerator GEMM: phi (regs) @ ktv
        ZERO16x4(acc);
        wgemm_regA(acc, ph, pl, pC);
#pragma unroll
        for (int f = 0; f < 16; f++) {
            outacc[f][0] += acc[f][0] * denA;
            outacc[f][1] += acc[f][1] * denA;
            outacc[f][2] += acc[f][2] * denB;
            outacc[f][3] += acc[f][3] * denB;
        }
        __syncthreads();   // all warps done reading pC(h)
        copy_img_async(pC, g_ktvImg + (size_t)hn * IMG2);  // overlaps next gemm1
        CP_COMMIT();
    }

    // comb (vss branch)
    CP_WAIT0();            // drain stray prefetches
    __syncthreads();
    copy_img_async(pA, g_simg + (size_t)t * IMG2);
    copy_img_async(pB, g_WcombImg);
    CP_COMMIT();
    CP_WAIT0();
    __syncthreads();
    {
        float acc[16][4];
        ZERO16x4(acc);
        wgemm(acc, pA, pB, mrow);
#pragma unroll
        for (int f = 0; f < 16; f++) {
            int c = ((f >> 1) << 4) + ((f & 1) << 3) + ((lane & 3) << 1);
            outacc[f][0] += acc[f][0] + sBc[c];
            outacc[f][1] += acc[f][1] + sBc[c + 1];
            outacc[f][2] += acc[f][2] + sBc[c];
            outacc[f][3] += acc[f][3] + sBc[c + 1];
        }
    }

    // time coordinate + store
    float ssa = 0.f, ssb = 0.f;
#pragma unroll
    for (int f = 0; f < 16; f++) {
        ssa += outacc[f][0] * outacc[f][0] + outacc[f][1] * outacc[f][1];
        ssb += outacc[f][2] * outacc[f][2] + outacc[f][3] * outacc[f][3];
    }
    ssa += __shfl_xor_sync(~0u, ssa, 1); ssa += __shfl_xor_sync(~0u, ssa, 2);
    ssb += __shfl_xor_sync(~0u, ssb, 1); ssb += __shfl_xor_sync(~0u, ssb, 2);
    float* rowA = out + (size_t)(n0 + grA) * 129;
    float* rowB = out + (size_t)(n0 + grB) * 129;
    if ((lane & 3) == 0) {
        rowA[0] = sqrtf(ssa + 1.0f);
        rowB[0] = sqrtf(ssb + 1.0f);
    }
#pragma unroll
    for (int f = 0; f < 16; f++) {
        int c = ((f >> 1) << 4) + ((f & 1) << 3) + ((lane & 3) << 1);
        rowA[1 + c] = outacc[f][0];
        rowA[2 + c] = outacc[f][1];
        rowB[1 + c] = outacc[f][2];
        rowB[2 + c] = outacc[f][3];
    }
}

// ---------------- launch ----------------
extern "C" void kernel_launch(void* const* d_in, const int* in_sizes, int n_in,
                              void* d_out, int out_size) {
    const float* q     = (const float*)d_in[0];
    const float* src   = (const float*)d_in[1];
    const float* Wq    = (const float*)d_in[2];
    const float* Wqb   = (const float*)d_in[3];
    const float* Wk    = (const float*)d_in[4];
    const float* Wkb   = (const float*)d_in[5];
    const float* Wv    = (const float*)d_in[6];
    const float* Wvb   = (const float*)d_in[7];
    const float* vmap  = (const float*)d_in[8];
    const float* vmapb = (const float*)d_in[9];
    const float* ns    = (const float*)d_in[10];
    float* out = (float*)d_out;

    size_t sm2 = (size_t)3 * IMG2 + 512;           // ~209.4 KB
    size_t smc = (size_t)2 * IMG2 + 1024;          // ~140.3 KB
    size_t smq = (size_t)3 * IMG2 + 1536;          // ~210.4 KB
    size_t smw = (size_t)128 * PITCHF * 4;         // 67,584 B
    cudaFuncSetAttribute(k2_kv,    cudaFuncAttributeMaxDynamicSharedMemorySize, (int)sm2);
    cudaFuncSetAttribute(k2c_ktv,  cudaFuncAttributeMaxDynamicSharedMemorySize, (int)smc);
    cudaFuncSetAttribute(kq_fused, cudaFuncAttributeMaxDynamicSharedMemorySize, (int)smq);
    cudaFuncSetAttribute(kw_comb,  cudaFuncAttributeMaxDynamicSharedMemorySize, (int)smw);

    kprep<<<2 * NT + 24, 256>>>(q, src, Wq, Wk, Wv);
    kw_comb<<<16, 256, smw>>>(Wv, Wvb, vmap, vmapb);
    k2_kv<<<dim3(NC, H), 256, sm2>>>(Wkb, ns);
    k2b_reduce<<<(H * C * C) / 256, 256>>>();
    k2c_ktv<<<H, 256, smc>>>(Wvb);
    kq_fused<<<NT, 256, smq>>>(Wqb, ns, out);
}